// round 3
// baseline (speedup 1.0000x reference)
#include <cuda_runtime.h>
#include <cstdint>

// Problem constants
#define H       30
#define HP      32          // padded hidden (dims 30,31 are zero forever)
#define BATCHN  16384
#define SEQ     784
#define NC      10

// Launch geometry: 1 warp handles 1 pair of batch elements.
#define PAIRS    8          // pairs per block = warps per block
#define THREADS  256
#define TCHUNK   112        // time steps staged per chunk (784 = 7 * 112)
#define NCHUNK   7
#define XROW     18         // floats per time-row in xs (padded for bank spread)

typedef unsigned long long ull;

// ---- packed f32x2 helpers (FFMA2 path: 2 fp32 FMAs per instruction) ----
__device__ __forceinline__ ull ffma2(ull a, ull b, ull c) {
    ull d; asm("fma.rn.f32x2 %0, %1, %2, %3;" : "=l"(d) : "l"(a), "l"(b), "l"(c)); return d;
}
__device__ __forceinline__ ull fmul2(ull a, ull b) {
    ull d; asm("mul.rn.f32x2 %0, %1, %2;" : "=l"(d) : "l"(a), "l"(b)); return d;
}
__device__ __forceinline__ ull fadd2(ull a, ull b) {
    ull d; asm("add.rn.f32x2 %0, %1, %2;" : "=l"(d) : "l"(a), "l"(b)); return d;
}
__device__ __forceinline__ ull pack2(float lo, float hi) {
    ull d; asm("mov.b64 %0, {%1, %2};" : "=l"(d) : "f"(lo), "f"(hi)); return d;
}
__device__ __forceinline__ void unpack2(ull v, float& lo, float& hi) {
    asm("mov.b64 {%0, %1}, %2;" : "=f"(lo), "=f"(hi) : "l"(v));
}
__device__ __forceinline__ float hsum2(ull v) {
    float lo, hi; unpack2(v, lo, hi); return lo + hi;
}
// modReLU scalar: sign(z) * max(|z| + b, 0)
__device__ __forceinline__ float modrelu(float z, float b) {
    float m = fmaxf(fabsf(z) + b, 0.0f);
    unsigned r = __float_as_uint(m) | (__float_as_uint(z) & 0x80000000u);
    return __uint_as_float(r);
}

__global__ __launch_bounds__(THREADS)
void rnn_modrelu_kernel(const float* __restrict__ inputs,   // [B, SEQ]
                        const float* __restrict__ W_ih,     // [H, 1]
                        const float* __restrict__ W_hh,     // [H, H]
                        const float* __restrict__ b_mod,    // [H]
                        const float* __restrict__ W_lin,    // [NC, H]
                        const float* __restrict__ b_lin,    // [NC]
                        float* __restrict__ out)            // [B, NC]
{
    // Staged inputs: xs[i*XROW + 2w] = x_A(t), xs[i*XROW + 2w + 1] = x_B(t).
    __shared__ __align__(16) float xs[TCHUNK * XROW];
    // Per-warp double-buffered hidden state, UNPACKED per element:
    // h_sh[warp][buf][elem][dim], dims 30,31 stay 0 forever.
    __shared__ __align__(16) float h_sh[PAIRS][2][2][HP];

    const int tid  = threadIdx.x;
    const int w    = tid >> 5;
    const int lane = tid & 31;
    const bool active = (lane < H);
    const int j = active ? lane : (H - 1);     // shadow row; lanes 30/31 never write

    const int b0 = (blockIdx.x * PAIRS + w) * 2;   // first batch element of the pair

    // --- per-lane weights, packed over k (NO duplication): 16 ulls = 32 regs ---
    const float wihj = W_ih[j];
    const float bj   = b_mod[j];
    float wr[HP];
#pragma unroll
    for (int k = 0; k < H; k++) wr[k] = W_hh[j * H + k];
    wr[30] = 0.0f; wr[31] = 0.0f;
    ull wp[HP / 2];
#pragma unroll
    for (int k = 0; k < HP / 2; k++) wp[k] = pack2(wr[2 * k], wr[2 * k + 1]);

    // init hidden state buffers to zero (h0 = 0, padding dims = 0)
    h_sh[w][0][0][lane] = 0.0f;
    h_sh[w][0][1][lane] = 0.0f;
    h_sh[w][1][0][lane] = 0.0f;
    h_sh[w][1][1][lane] = 0.0f;
    __syncwarp();

    const float* inBase0 = inputs + (size_t)(blockIdx.x * PAIRS * 2) * SEQ;

    for (int ch = 0; ch < NCHUNK; ch++) {
        __syncthreads();  // all warps done reading previous xs chunk
        const float* inBase = inBase0 + ch * TCHUNK;
        for (int e = tid; e < 16 * TCHUNK; e += THREADS) {
            int r = e / TCHUNK;          // local batch row 0..15
            int i = e - r * TCHUNK;      // time within chunk
            xs[i * XROW + r] = inBase[(size_t)r * SEQ + i];
        }
        __syncthreads();

#pragma unroll 2
        for (int i = 0; i < TCHUNK; i++) {
            const int rb = i & 1;        // chunk len even, so parity tracks i
            const ulonglong2* pa = (const ulonglong2*)&h_sh[w][rb][0][0];  // elem A
            const ulonglong2* pb = (const ulonglong2*)&h_sh[w][rb][1][0];  // elem B

            // broadcast inputs for this pair at step t
            float xA, xB;
            unpack2(*(const ull*)&xs[i * XROW + 2 * w], xA, xB);

            // dot(W_hh[j,:], h) for both elements; 2 chains each for ILP
            ull a0 = 0ull, a1 = 0ull, c0 = 0ull, c1 = 0ull;
#pragma unroll
            for (int q = 0; q < HP / 8; q++) {       // 4 iters, 2x LDS.128 each
                ulonglong2 va = pa[2 * q];
                ulonglong2 vb = pb[2 * q];
                a0 = ffma2(wp[4 * q],     va.x, a0);
                a1 = ffma2(wp[4 * q + 1], va.y, a1);
                c0 = ffma2(wp[4 * q],     vb.x, c0);
                c1 = ffma2(wp[4 * q + 1], vb.y, c1);
                va = pa[2 * q + 1];
                vb = pb[2 * q + 1];
                a0 = ffma2(wp[4 * q + 2], va.x, a0);
                a1 = ffma2(wp[4 * q + 3], va.y, a1);
                c0 = ffma2(wp[4 * q + 2], vb.x, c0);
                c1 = ffma2(wp[4 * q + 3], vb.y, c1);
            }
            const float zA = fmaf(xA, wihj, hsum2(fadd2(a0, a1)));
            const float zB = fmaf(xB, wihj, hsum2(fadd2(c0, c1)));

            const float hA = modrelu(zA, bj);
            const float hB = modrelu(zB, bj);

            if (active) {
                h_sh[w][1 - rb][0][j] = hA;
                h_sh[w][1 - rb][1][j] = hB;
            }
            __syncwarp();
        }
    }

    // Final state is in buffer 0 (784 even steps; each 112-chunk ends in buf 0).
    const float* hA = &h_sh[w][0][0][0];
    const float* hB = &h_sh[w][0][1][0];
    if (lane < NC) {
        const int c = lane;
        float sA = b_lin[c], sB = sA;
#pragma unroll
        for (int k = 0; k < H; k++) {
            const float wl = W_lin[c * H + k];
            sA = fmaf(wl, hA[k], sA);
            sB = fmaf(wl, hB[k], sB);
        }
        out[(size_t)b0 * NC + c]       = sA;
        out[(size_t)(b0 + 1) * NC + c] = sB;
    }
}

extern "C" void kernel_launch(void* const* d_in, const int* in_sizes, int n_in,
                              void* d_out, int out_size) {
    const float* inputs = (const float*)d_in[0];
    const float* W_ih   = (const float*)d_in[1];
    const float* W_hh   = (const float*)d_in[2];
    const float* b_mod  = (const float*)d_in[3];
    const float* W_lin  = (const float*)d_in[4];
    const float* b_lin  = (const float*)d_in[5];
    float* out = (float*)d_out;

    const int nblocks = BATCHN / (2 * PAIRS);   // 1024
    rnn_modrelu_kernel<<<nblocks, THREADS>>>(inputs, W_ih, W_hh, b_mod,
                                             W_lin, b_lin, out);
}

// round 4
// speedup vs baseline: 1.0774x; 1.0774x over previous
#include <cuda_runtime.h>
#include <cstdint>

#define H       30
#define HP      32
#define BATCHN  16384
#define SEQ     784
#define NC      10

#define WARPS    8          // warps per block; each warp: 2 batch elements
#define THREADS  256
#define TCHUNK   112        // 784 = 7 * 112
#define NCHUNK   7
#define XROW     18

typedef unsigned long long ull;

__device__ __forceinline__ ull ffma2(ull a, ull b, ull c) {
    ull d; asm("fma.rn.f32x2 %0, %1, %2, %3;" : "=l"(d) : "l"(a), "l"(b), "l"(c)); return d;
}
__device__ __forceinline__ ull fadd2(ull a, ull b) {
    ull d; asm("add.rn.f32x2 %0, %1, %2;" : "=l"(d) : "l"(a), "l"(b)); return d;
}
__device__ __forceinline__ ull pack2(float lo, float hi) {
    ull d; asm("mov.b64 %0, {%1, %2};" : "=l"(d) : "f"(lo), "f"(hi)); return d;
}
__device__ __forceinline__ void unpack2(ull v, float& lo, float& hi) {
    asm("mov.b64 {%0, %1}, %2;" : "=f"(lo), "=f"(hi) : "l"(v));
}
// 64-bit shuffle-xor via two 32-bit shuffles
__device__ __forceinline__ ull shflx2(ull v, int m) {
    float lo, hi; unpack2(v, lo, hi);
    lo = __shfl_xor_sync(0xFFFFFFFFu, lo, m);
    hi = __shfl_xor_sync(0xFFFFFFFFu, hi, m);
    return pack2(lo, hi);
}
__device__ __forceinline__ float modrelu(float z, float b) {
    float m = fmaxf(fabsf(z) + b, 0.0f);
    unsigned r = __float_as_uint(m) | (__float_as_uint(z) & 0x80000000u);
    return __uint_as_float(r);
}

__global__ __launch_bounds__(THREADS)
void rnn_modrelu_kernel(const float* __restrict__ inputs,   // [B, SEQ]
                        const float* __restrict__ W_ih,     // [H, 1]
                        const float* __restrict__ W_hh,     // [H, H]
                        const float* __restrict__ b_mod,    // [H]
                        const float* __restrict__ W_lin,    // [NC, H]
                        const float* __restrict__ b_lin,    // [NC]
                        float* __restrict__ out)            // [B, NC]
{
    __shared__ __align__(16) float xs[TCHUNK * XROW];
    // h_sh[warp][buf][elem][dim]; dims 30,31 forced to 0 each step.
    __shared__ __align__(128) float h_sh[WARPS][2][2][HP];

    const int tid  = threadIdx.x;
    const int w    = tid >> 5;
    const int lane = tid & 31;
    const int j    = lane & 15;     // dim base
    const int s    = lane >> 4;     // k-half: k in [16s, 16s+16)
    const int d    = j + 16 * s;    // dim this lane FINALIZES
    const bool dok = (d < H);

    const int b0 = (blockIdx.x * WARPS + w) * 2;   // first batch element

    // Per-lane weights: rows j and j+16, k-half s only, packed along k.
    // wp0[i] = (W[j][ks+2i], W[j][ks+2i+1]),  wp1 same for row j+16.
    ull wp0[8], wp1[8];
    const int ks = 16 * s;
    const int r1 = j + 16;
#pragma unroll
    for (int i = 0; i < 8; i++) {
        int k0 = ks + 2 * i, k1 = k0 + 1;
        float a0 = (k0 < H) ? W_hh[j * H + k0] : 0.0f;
        float a1 = (k1 < H) ? W_hh[j * H + k1] : 0.0f;
        wp0[i] = pack2(a0, a1);
        float c0 = (r1 < H && k0 < H) ? W_hh[r1 * H + k0] : 0.0f;
        float c1 = (r1 < H && k1 < H) ? W_hh[r1 * H + k1] : 0.0f;
        wp1[i] = pack2(c0, c1);
    }
    const float wihd = dok ? W_ih[d]  : 0.0f;
    const float bd   = dok ? b_mod[d] : 0.0f;

    // init hidden state buffers to zero
    h_sh[w][0][0][lane] = 0.0f;
    h_sh[w][0][1][lane] = 0.0f;
    h_sh[w][1][0][lane] = 0.0f;
    h_sh[w][1][1][lane] = 0.0f;
    __syncwarp();

    const float* inBase0 = inputs + (size_t)(blockIdx.x * WARPS * 2) * SEQ;

    for (int ch = 0; ch < NCHUNK; ch++) {
        __syncthreads();
        const float* inBase = inBase0 + ch * TCHUNK;
        for (int e = tid; e < 16 * TCHUNK; e += THREADS) {
            int r = e / TCHUNK;
            int i = e - r * TCHUNK;
            xs[i * XROW + r] = inBase[(size_t)r * SEQ + i];
        }
        __syncthreads();

#pragma unroll 2
        for (int i = 0; i < TCHUNK; i++) {
            const int rb = i & 1;

            float xA, xB;
            unpack2(*(const ull*)&xs[i * XROW + 2 * w], xA, xB);

            float hvA, hvB;
#pragma unroll
            for (int e = 0; e < 2; e++) {
                // load this lane's k-half of h for element e: 4x LDS.128,
                // two address groups (s=0 / s=1) per instruction, bank-disjoint.
                const ulonglong2* hp =
                    (const ulonglong2*)&h_sh[w][rb][e][ks];
                ulonglong2 q0 = hp[0];
                ulonglong2 q1 = hp[1];
                ulonglong2 q2 = hp[2];
                ulonglong2 q3 = hp[3];

                // partial dots for dims j (P0) and j+16 (P1) over this k-half
                ull P0 = ffma2(wp0[0], q0.x, 0ull);
                ull P1 = ffma2(wp1[0], q0.x, 0ull);
                P0 = ffma2(wp0[1], q0.y, P0);  P1 = ffma2(wp1[1], q0.y, P1);
                P0 = ffma2(wp0[2], q1.x, P0);  P1 = ffma2(wp1[2], q1.x, P1);
                P0 = ffma2(wp0[3], q1.y, P0);  P1 = ffma2(wp1[3], q1.y, P1);
                P0 = ffma2(wp0[4], q2.x, P0);  P1 = ffma2(wp1[4], q2.x, P1);
                P0 = ffma2(wp0[5], q2.y, P0);  P1 = ffma2(wp1[5], q2.y, P1);
                P0 = ffma2(wp0[6], q3.x, P0);  P1 = ffma2(wp1[6], q3.x, P1);
                P0 = ffma2(wp0[7], q3.y, P0);  P1 = ffma2(wp1[7], q3.y, P1);

                // wait: P0/P1 are f32x2 over (even-k, odd-k) partial sums of
                // SCALAR element e?  No: h here is scalar per element, packed
                // pairs are (h_{2k}, h_{2k+1}).  P is f32x2 partial over k.
                // Exchange with the other k-half (lane ^ 16):
                const ull send = (s == 0) ? P1 : P0;
                const ull keep = (s == 0) ? P0 : P1;
                const ull Z2   = fadd2(keep, shflx2(send, 16));
                float zl, zh; unpack2(Z2, zl, zh);
                const float x  = (e == 0) ? xA : xB;
                const float z  = fmaf(x, wihd, zl + zh);
                const float hv = dok ? modrelu(z, bd) : 0.0f;
                if (e == 0) hvA = hv; else hvB = hv;
            }

            h_sh[w][1 - rb][0][d] = hvA;
            h_sh[w][1 - rb][1][d] = hvB;
            __syncwarp();
        }
    }

    // Final state in buffer 0 (even chunk length).
    const float* hA = &h_sh[w][0][0][0];
    const float* hB = &h_sh[w][0][1][0];
    if (lane < NC) {
        const int c = lane;
        float sA = b_lin[c], sB = sA;
#pragma unroll
        for (int k = 0; k < H; k++) {
            const float wl = W_lin[c * H + k];
            sA = fmaf(wl, hA[k], sA);
            sB = fmaf(wl, hB[k], sB);
        }
        out[(size_t)b0 * NC + c]       = sA;
        out[(size_t)(b0 + 1) * NC + c] = sB;
    }
}

extern "C" void kernel_launch(void* const* d_in, const int* in_sizes, int n_in,
                              void* d_out, int out_size) {
    const float* inputs = (const float*)d_in[0];
    const float* W_ih   = (const float*)d_in[1];
    const float* W_hh   = (const float*)d_in[2];
    const float* b_mod  = (const float*)d_in[3];
    const float* W_lin  = (const float*)d_in[4];
    const float* b_lin  = (const float*)d_in[5];
    float* out = (float*)d_out;

    const int nblocks = BATCHN / (2 * WARPS);   // 1024
    rnn_modrelu_kernel<<<nblocks, THREADS>>>(inputs, W_ih, W_hh, b_mod,
                                             W_lin, b_lin, out);
}